// round 8
// baseline (speedup 1.0000x reference)
#include <cuda_runtime.h>
#include <mma.h>
#include <cstdint>
#include <cstddef>

using namespace nvcuda;

#define B_ 64
#define S_ 2048
#define E_ 512
#define C_ 512
#define H_ 256

// ---------------- scratch (static device globals; no allocation) ----------------
__device__ float g_ctx[B_ * H_];        // ctx_feat + b_ctx + b_word  [B,H]
__device__ float g_scores[B_ * S_];     // pre-softmax scores         [B,S]
__device__ float g_attn[B_ * S_];       // normalized attention       [B,S]
__device__ float g_part[8 * B_ * E_];   // weighted-sum partials      [8,B,E]

// ---------------------------------------------------------------------------
// Kernel 1: ctx_feat[b,h] = b_ctx[h] + b_word[h] + sum_c context[b,c]*W_ctx[h,c]
// (b_word folded in here so the GEMM epilogue only adds one vector)
// ---------------------------------------------------------------------------
__global__ void ctx_kernel(const float* __restrict__ context,
                           const float* __restrict__ W_ctx,
                           const float* __restrict__ b_ctx,
                           const float* __restrict__ b_word) {
    int b = blockIdx.x, h = threadIdx.x;
    const float4* wr = reinterpret_cast<const float4*>(W_ctx + (size_t)h * C_);
    const float4* cr = reinterpret_cast<const float4*>(context + (size_t)b * C_);
    float acc = b_ctx[h] + b_word[h];
#pragma unroll 8
    for (int i = 0; i < C_ / 4; i++) {
        float4 w = wr[i];
        float4 c = cr[i];
        acc += w.x * c.x + w.y * c.y + w.z * c.z + w.w * c.w;
    }
    g_ctx[b * H_ + h] = acc;
}

// ---------------------------------------------------------------------------
// Kernel 2: fused word_feat GEMM (tf32 wmma) + tanh + dot(w_hidden) -> scores
// Block = (s-tile of 64, batch b). M=64, N=256 (all H), K=512.
// 8 warps: warp_m = wid&1 (32 rows), warp_n = wid>>1 (64 cols).
// Skips fully-masked tiles (s0 >= length).
// ---------------------------------------------------------------------------
#define LDAB 36   // smem leading dim for A/B tiles (mult of 4, bank-staggered)
#define LDWF 132  // smem leading dim for word_feat half-buffer

__global__ __launch_bounds__(256) void scores_kernel(
    const float* __restrict__ A,         // [B,S,E]
    const float* __restrict__ Ww,        // W_word [H,E]
    const int* __restrict__ lengths,
    const float* __restrict__ w_hidden) {
    int b = blockIdx.y;
    int s0 = blockIdx.x * 64;
    int len = lengths[b];
    if (s0 >= len) return;  // uniform early exit: scores beyond length are never used

    __shared__ float sm[11520];          // 46080 B: As(64x36) + Bs(256x36); reused as wf buf
    float* As = sm;
    float* Bs = sm + 64 * LDAB;

    int tid = threadIdx.x;
    int lane = tid & 31, wid = tid >> 5;
    int wm = wid & 1, wn = wid >> 1;

    wmma::fragment<wmma::accumulator, 16, 16, 8, float> acc[2][4];
#pragma unroll
    for (int mi = 0; mi < 2; mi++)
#pragma unroll
        for (int ni = 0; ni < 4; ni++) wmma::fill_fragment(acc[mi][ni], 0.0f);

    const float* Ab = A + ((size_t)b * S_ + s0) * E_;

    for (int kc = 0; kc < 16; kc++) {
        int k0 = kc * 32;
        // stage A tile 64x32 (tf32-rounded)
#pragma unroll
        for (int i = 0; i < 2; i++) {
            int idx = tid + i * 256;
            int r = idx >> 3, c4 = (idx & 7) * 4;
            float4 v = *reinterpret_cast<const float4*>(Ab + (size_t)r * E_ + k0 + c4);
            float* d = As + r * LDAB + c4;
            d[0] = wmma::__float_to_tf32(v.x);
            d[1] = wmma::__float_to_tf32(v.y);
            d[2] = wmma::__float_to_tf32(v.z);
            d[3] = wmma::__float_to_tf32(v.w);
        }
        // stage B tile: W_word rows h=0..255, cols k0..k0+31 -> Bs[h][c] (col-major view: (k,n)->n*ld+k)
#pragma unroll
        for (int i = 0; i < 8; i++) {
            int idx = tid + i * 256;
            int h = idx >> 3, c4 = (idx & 7) * 4;
            float4 v = *reinterpret_cast<const float4*>(Ww + (size_t)h * E_ + k0 + c4);
            float* d = Bs + h * LDAB + c4;
            d[0] = wmma::__float_to_tf32(v.x);
            d[1] = wmma::__float_to_tf32(v.y);
            d[2] = wmma::__float_to_tf32(v.z);
            d[3] = wmma::__float_to_tf32(v.w);
        }
        __syncthreads();
#pragma unroll
        for (int kk = 0; kk < 4; kk++) {
            int ko = kk * 8;
            wmma::fragment<wmma::matrix_a, 16, 16, 8, wmma::precision::tf32, wmma::row_major> af[2];
            wmma::fragment<wmma::matrix_b, 16, 16, 8, wmma::precision::tf32, wmma::col_major> bf[4];
            wmma::load_matrix_sync(af[0], As + (wm * 32) * LDAB + ko, LDAB);
            wmma::load_matrix_sync(af[1], As + (wm * 32 + 16) * LDAB + ko, LDAB);
#pragma unroll
            for (int ni = 0; ni < 4; ni++)
                wmma::load_matrix_sync(bf[ni], Bs + (wn * 64 + ni * 16) * LDAB + ko, LDAB);
#pragma unroll
            for (int mi = 0; mi < 2; mi++)
#pragma unroll
                for (int ni = 0; ni < 4; ni++)
                    wmma::mma_sync(acc[mi][ni], af[mi], bf[ni], acc[mi][ni]);
        }
        __syncthreads();
    }

    // epilogue: two column-halves through a 64x132 smem buffer (fits under As+Bs footprint)
    float psum[8];
#pragma unroll
    for (int rr = 0; rr < 8; rr++) psum[rr] = 0.0f;
    const float* ctxp = g_ctx + b * H_;

#pragma unroll
    for (int hh = 0; hh < 2; hh++) {
        __syncthreads();
        if ((wn >> 1) == hh) {
            int cw = (wn & 1) * 64;
#pragma unroll
            for (int mi = 0; mi < 2; mi++)
#pragma unroll
                for (int ni = 0; ni < 4; ni++)
                    wmma::store_matrix_sync(sm + (wm * 32 + mi * 16) * LDWF + cw + ni * 16,
                                            acc[mi][ni], LDWF, wmma::mem_row_major);
        }
        __syncthreads();
#pragma unroll
        for (int rr = 0; rr < 8; rr++) {
            int r = wid * 8 + rr;
#pragma unroll
            for (int j = 0; j < 4; j++) {
                int c = lane + j * 32;
                float x = sm[r * LDWF + c] + ctxp[hh * 128 + c];
                // accurate tanh via fast exp (clamped; |x| large -> +/-1 exactly)
                x = fminf(fmaxf(x, -15.0f), 15.0f);
                float e2 = __expf(2.0f * x);
                float th = __fdividef(e2 - 1.0f, e2 + 1.0f);
                psum[rr] += th * w_hidden[hh * 128 + c];
            }
        }
    }
#pragma unroll
    for (int rr = 0; rr < 8; rr++) {
        float s = psum[rr];
#pragma unroll
        for (int o = 16; o > 0; o >>= 1) s += __shfl_xor_sync(0xffffffffu, s, o);
        if (lane == 0) g_scores[(size_t)b * S_ + wid * 8 + rr + s0] = s;
    }
}

// ---------------------------------------------------------------------------
// Kernel 3: masked softmax. Exact algebra: softmax(all)*mask renormalized ==
// exp(s-m_valid)/L_valid on valid prefix (1e-10 term <= 1e-10 relative since L>=1).
// ---------------------------------------------------------------------------
__global__ __launch_bounds__(256) void attn_softmax_kernel(const int* __restrict__ lengths,
                                                           float* __restrict__ attn_out) {
    int b = blockIdx.x, tid = threadIdx.x;
    int lane = tid & 31, wid = tid >> 5;
    int len = lengths[b];
    const float* sc = g_scores + (size_t)b * S_;

    float v[8];
    float m = -1e30f;
#pragma unroll
    for (int i = 0; i < 8; i++) {
        int s = tid + i * 256;
        v[i] = (s < len) ? sc[s] : -1e30f;
        m = fmaxf(m, v[i]);
    }
#pragma unroll
    for (int o = 16; o > 0; o >>= 1) m = fmaxf(m, __shfl_xor_sync(0xffffffffu, m, o));
    __shared__ float red[8];
    if (lane == 0) red[wid] = m;
    __syncthreads();
    float mm = red[0];
#pragma unroll
    for (int i = 1; i < 8; i++) mm = fmaxf(mm, red[i]);

    float t[8];
    float L = 0.0f;
#pragma unroll
    for (int i = 0; i < 8; i++) {
        int s = tid + i * 256;
        t[i] = (s < len) ? __expf(v[i] - mm) : 0.0f;
        L += t[i];
    }
#pragma unroll
    for (int o = 16; o > 0; o >>= 1) L += __shfl_xor_sync(0xffffffffu, L, o);
    __syncthreads();
    if (lane == 0) red[wid] = L;
    __syncthreads();
    float Lt = 0.0f;
#pragma unroll
    for (int i = 0; i < 8; i++) Lt += red[i];
    float inv = __fdividef(1.0f, Lt);

#pragma unroll
    for (int i = 0; i < 8; i++) {
        int s = tid + i * 256;
        float a = t[i] * inv;
        g_attn[(size_t)b * S_ + s] = a;
        if (attn_out) attn_out[(size_t)b * S_ + s] = a;
    }
}

// ---------------------------------------------------------------------------
// Kernel 4: weighted sum partials. Block (q, b): s-chunk of 256; iterates only
// the valid prefix (uniform bound per block -> full MLP, no divergence).
// ---------------------------------------------------------------------------
__global__ __launch_bounds__(128) void wsum_kernel(const float* __restrict__ A,
                                                   const int* __restrict__ lengths) {
    int q = blockIdx.x, b = blockIdx.y;
    int tid = threadIdx.x;
    int len = lengths[b];
    int nv = len - q * 256;
    nv = (nv > 256) ? 256 : nv;

    float4 acc = make_float4(0.f, 0.f, 0.f, 0.f);
    if (nv > 0) {
        const float* Ab = A + ((size_t)b * S_ + q * 256) * E_ + tid * 4;
        const float* at = g_attn + (size_t)b * S_ + q * 256;
#pragma unroll 4
        for (int s = 0; s < nv; s++) {
            float w = at[s];
            float4 a = *reinterpret_cast<const float4*>(Ab + (size_t)s * E_);
            acc.x += w * a.x;
            acc.y += w * a.y;
            acc.z += w * a.z;
            acc.w += w * a.w;
        }
    }
    *reinterpret_cast<float4*>(g_part + ((size_t)(q * B_ + b)) * E_ + tid * 4) = acc;
}

// ---------------------------------------------------------------------------
// Kernel 5: reduce 8 partials -> attention_features
// ---------------------------------------------------------------------------
__global__ void reduce_kernel(float* __restrict__ feat) {
    int b = blockIdx.x, e = threadIdx.x;
    float s = 0.0f;
#pragma unroll
    for (int q = 0; q < 8; q++) s += g_part[((size_t)(q * B_ + b)) * E_ + e];
    feat[b * E_ + e] = s;
}

// ---------------------------------------------------------------------------
extern "C" void kernel_launch(void* const* d_in, const int* in_sizes, int n_in,
                              void* d_out, int out_size) {
    const float* A        = (const float*)d_in[0];  // encoder_word_embeds [B,S,E]
    const int*   lengths  = (const int*)d_in[1];    // encoder_lengths [B]
    const float* context  = (const float*)d_in[2];  // context_state [B,C]
    const float* W_word   = (const float*)d_in[3];  // [H,E]
    const float* b_word   = (const float*)d_in[4];  // [H]
    const float* W_ctx    = (const float*)d_in[5];  // [H,C]
    const float* b_ctx    = (const float*)d_in[6];  // [H]
    const float* w_hidden = (const float*)d_in[7];  // [H]

    float* out = (float*)d_out;
    float* feat_out = out;                                        // [B,E] first
    float* attn_out = (out_size >= B_ * E_ + B_ * S_) ? out + B_ * E_ : nullptr;  // [B,S] second

    ctx_kernel<<<B_, H_>>>(context, W_ctx, b_ctx, b_word);

    dim3 g2(S_ / 64, B_);
    scores_kernel<<<g2, 256>>>(A, W_word, lengths, w_hidden);

    attn_softmax_kernel<<<B_, 256>>>(lengths, attn_out);

    dim3 g4(8, B_);
    wsum_kernel<<<g4, 128>>>(A, lengths);

    reduce_kernel<<<B_, E_>>>(feat_out);
}

// round 9
// speedup vs baseline: 1.0005x; 1.0005x over previous
#include <cuda_runtime.h>
#include <mma.h>
#include <cstdint>
#include <cstddef>

using namespace nvcuda;

#define B_ 64
#define S_ 2048
#define E_ 512
#define C_ 512
#define H_ 256

// ---------------- scratch (static device globals; no allocation) ----------------
__device__ float g_ctx[B_ * H_];        // ctx_feat + b_ctx + b_word  [B,H]
__device__ float g_scores[B_ * S_];     // pre-softmax scores         [B,S]
__device__ float g_attn[B_ * S_];       // normalized attention       [B,S]
__device__ float g_part[8 * B_ * E_];   // weighted-sum partials      [8,B,E]

// ---------------------------------------------------------------------------
// Kernel 1: ctx_feat[b,h] = b_ctx[h] + b_word[h] + sum_c context[b,c]*W_ctx[h,c]
// (b_word folded in here so the GEMM epilogue only adds one vector)
// ---------------------------------------------------------------------------
__global__ void ctx_kernel(const float* __restrict__ context,
                           const float* __restrict__ W_ctx,
                           const float* __restrict__ b_ctx,
                           const float* __restrict__ b_word) {
    int b = blockIdx.x, h = threadIdx.x;
    const float4* wr = reinterpret_cast<const float4*>(W_ctx + (size_t)h * C_);
    const float4* cr = reinterpret_cast<const float4*>(context + (size_t)b * C_);
    float acc = b_ctx[h] + b_word[h];
#pragma unroll 8
    for (int i = 0; i < C_ / 4; i++) {
        float4 w = wr[i];
        float4 c = cr[i];
        acc += w.x * c.x + w.y * c.y + w.z * c.z + w.w * c.w;
    }
    g_ctx[b * H_ + h] = acc;
}

// ---------------------------------------------------------------------------
// Kernel 2: fused word_feat GEMM (tf32 wmma) + tanh + dot(w_hidden) -> scores
// Block = (s-tile of 64, batch b). M=64, N=256 (all H), K=512.
// 8 warps: warp_m = wid&1 (32 rows), warp_n = wid>>1 (64 cols).
// Skips fully-masked tiles (s0 >= length).
// ---------------------------------------------------------------------------
#define LDAB 36   // smem leading dim for A/B tiles (mult of 4, bank-staggered)
#define LDWF 132  // smem leading dim for word_feat half-buffer

__global__ __launch_bounds__(256) void scores_kernel(
    const float* __restrict__ A,         // [B,S,E]
    const float* __restrict__ Ww,        // W_word [H,E]
    const int* __restrict__ lengths,
    const float* __restrict__ w_hidden) {
    int b = blockIdx.y;
    int s0 = blockIdx.x * 64;
    int len = lengths[b];
    if (s0 >= len) return;  // uniform early exit: scores beyond length are never used

    __shared__ float sm[11520];          // 46080 B: As(64x36) + Bs(256x36); reused as wf buf
    float* As = sm;
    float* Bs = sm + 64 * LDAB;

    int tid = threadIdx.x;
    int lane = tid & 31, wid = tid >> 5;
    int wm = wid & 1, wn = wid >> 1;

    wmma::fragment<wmma::accumulator, 16, 16, 8, float> acc[2][4];
#pragma unroll
    for (int mi = 0; mi < 2; mi++)
#pragma unroll
        for (int ni = 0; ni < 4; ni++) wmma::fill_fragment(acc[mi][ni], 0.0f);

    const float* Ab = A + ((size_t)b * S_ + s0) * E_;

    for (int kc = 0; kc < 16; kc++) {
        int k0 = kc * 32;
        // stage A tile 64x32 (tf32-rounded)
#pragma unroll
        for (int i = 0; i < 2; i++) {
            int idx = tid + i * 256;
            int r = idx >> 3, c4 = (idx & 7) * 4;
            float4 v = *reinterpret_cast<const float4*>(Ab + (size_t)r * E_ + k0 + c4);
            float* d = As + r * LDAB + c4;
            d[0] = wmma::__float_to_tf32(v.x);
            d[1] = wmma::__float_to_tf32(v.y);
            d[2] = wmma::__float_to_tf32(v.z);
            d[3] = wmma::__float_to_tf32(v.w);
        }
        // stage B tile: W_word rows h=0..255, cols k0..k0+31 -> Bs[h][c] (col-major view: (k,n)->n*ld+k)
#pragma unroll
        for (int i = 0; i < 8; i++) {
            int idx = tid + i * 256;
            int h = idx >> 3, c4 = (idx & 7) * 4;
            float4 v = *reinterpret_cast<const float4*>(Ww + (size_t)h * E_ + k0 + c4);
            float* d = Bs + h * LDAB + c4;
            d[0] = wmma::__float_to_tf32(v.x);
            d[1] = wmma::__float_to_tf32(v.y);
            d[2] = wmma::__float_to_tf32(v.z);
            d[3] = wmma::__float_to_tf32(v.w);
        }
        __syncthreads();
#pragma unroll
        for (int kk = 0; kk < 4; kk++) {
            int ko = kk * 8;
            wmma::fragment<wmma::matrix_a, 16, 16, 8, wmma::precision::tf32, wmma::row_major> af[2];
            wmma::fragment<wmma::matrix_b, 16, 16, 8, wmma::precision::tf32, wmma::col_major> bf[4];
            wmma::load_matrix_sync(af[0], As + (wm * 32) * LDAB + ko, LDAB);
            wmma::load_matrix_sync(af[1], As + (wm * 32 + 16) * LDAB + ko, LDAB);
#pragma unroll
            for (int ni = 0; ni < 4; ni++)
                wmma::load_matrix_sync(bf[ni], Bs + (wn * 64 + ni * 16) * LDAB + ko, LDAB);
#pragma unroll
            for (int mi = 0; mi < 2; mi++)
#pragma unroll
                for (int ni = 0; ni < 4; ni++)
                    wmma::mma_sync(acc[mi][ni], af[mi], bf[ni], acc[mi][ni]);
        }
        __syncthreads();
    }

    // epilogue: two column-halves through a 64x132 smem buffer (fits under As+Bs footprint)
    float psum[8];
#pragma unroll
    for (int rr = 0; rr < 8; rr++) psum[rr] = 0.0f;
    const float* ctxp = g_ctx + b * H_;

#pragma unroll
    for (int hh = 0; hh < 2; hh++) {
        __syncthreads();
        if ((wn >> 1) == hh) {
            int cw = (wn & 1) * 64;
#pragma unroll
            for (int mi = 0; mi < 2; mi++)
#pragma unroll
                for (int ni = 0; ni < 4; ni++)
                    wmma::store_matrix_sync(sm + (wm * 32 + mi * 16) * LDWF + cw + ni * 16,
                                            acc[mi][ni], LDWF, wmma::mem_row_major);
        }
        __syncthreads();
#pragma unroll
        for (int rr = 0; rr < 8; rr++) {
            int r = wid * 8 + rr;
#pragma unroll
            for (int j = 0; j < 4; j++) {
                int c = lane + j * 32;
                float x = sm[r * LDWF + c] + ctxp[hh * 128 + c];
                // accurate tanh via fast exp (clamped; |x| large -> +/-1 exactly)
                x = fminf(fmaxf(x, -15.0f), 15.0f);
                float e2 = __expf(2.0f * x);
                float th = __fdividef(e2 - 1.0f, e2 + 1.0f);
                psum[rr] += th * w_hidden[hh * 128 + c];
            }
        }
    }
#pragma unroll
    for (int rr = 0; rr < 8; rr++) {
        float s = psum[rr];
#pragma unroll
        for (int o = 16; o > 0; o >>= 1) s += __shfl_xor_sync(0xffffffffu, s, o);
        if (lane == 0) g_scores[(size_t)b * S_ + wid * 8 + rr + s0] = s;
    }
}

// ---------------------------------------------------------------------------
// Kernel 3: masked softmax. Exact algebra: softmax(all)*mask renormalized ==
// exp(s-m_valid)/L_valid on valid prefix (1e-10 term <= 1e-10 relative since L>=1).
// ---------------------------------------------------------------------------
__global__ __launch_bounds__(256) void attn_softmax_kernel(const int* __restrict__ lengths,
                                                           float* __restrict__ attn_out) {
    int b = blockIdx.x, tid = threadIdx.x;
    int lane = tid & 31, wid = tid >> 5;
    int len = lengths[b];
    const float* sc = g_scores + (size_t)b * S_;

    float v[8];
    float m = -1e30f;
#pragma unroll
    for (int i = 0; i < 8; i++) {
        int s = tid + i * 256;
        v[i] = (s < len) ? sc[s] : -1e30f;
        m = fmaxf(m, v[i]);
    }
#pragma unroll
    for (int o = 16; o > 0; o >>= 1) m = fmaxf(m, __shfl_xor_sync(0xffffffffu, m, o));
    __shared__ float red[8];
    if (lane == 0) red[wid] = m;
    __syncthreads();
    float mm = red[0];
#pragma unroll
    for (int i = 1; i < 8; i++) mm = fmaxf(mm, red[i]);

    float t[8];
    float L = 0.0f;
#pragma unroll
    for (int i = 0; i < 8; i++) {
        int s = tid + i * 256;
        t[i] = (s < len) ? __expf(v[i] - mm) : 0.0f;
        L += t[i];
    }
#pragma unroll
    for (int o = 16; o > 0; o >>= 1) L += __shfl_xor_sync(0xffffffffu, L, o);
    __syncthreads();
    if (lane == 0) red[wid] = L;
    __syncthreads();
    float Lt = 0.0f;
#pragma unroll
    for (int i = 0; i < 8; i++) Lt += red[i];
    float inv = __fdividef(1.0f, Lt);

#pragma unroll
    for (int i = 0; i < 8; i++) {
        int s = tid + i * 256;
        float a = t[i] * inv;
        g_attn[(size_t)b * S_ + s] = a;
        if (attn_out) attn_out[(size_t)b * S_ + s] = a;
    }
}

// ---------------------------------------------------------------------------
// Kernel 4: weighted sum partials. Block (q, b): s-chunk of 256; iterates only
// the valid prefix (uniform bound per block -> full MLP, no divergence).
// ---------------------------------------------------------------------------
__global__ __launch_bounds__(128) void wsum_kernel(const float* __restrict__ A,
                                                   const int* __restrict__ lengths) {
    int q = blockIdx.x, b = blockIdx.y;
    int tid = threadIdx.x;
    int len = lengths[b];
    int nv = len - q * 256;
    nv = (nv > 256) ? 256 : nv;

    float4 acc = make_float4(0.f, 0.f, 0.f, 0.f);
    if (nv > 0) {
        const float* Ab = A + ((size_t)b * S_ + q * 256) * E_ + tid * 4;
        const float* at = g_attn + (size_t)b * S_ + q * 256;
#pragma unroll 4
        for (int s = 0; s < nv; s++) {
            float w = at[s];
            float4 a = *reinterpret_cast<const float4*>(Ab + (size_t)s * E_);
            acc.x += w * a.x;
            acc.y += w * a.y;
            acc.z += w * a.z;
            acc.w += w * a.w;
        }
    }
    *reinterpret_cast<float4*>(g_part + ((size_t)(q * B_ + b)) * E_ + tid * 4) = acc;
}

// ---------------------------------------------------------------------------
// Kernel 5: reduce 8 partials -> attention_features
// ---------------------------------------------------------------------------
__global__ void reduce_kernel(float* __restrict__ feat) {
    int b = blockIdx.x, e = threadIdx.x;
    float s = 0.0f;
#pragma unroll
    for (int q = 0; q < 8; q++) s += g_part[((size_t)(q * B_ + b)) * E_ + e];
    feat[b * E_ + e] = s;
}

// ---------------------------------------------------------------------------
extern "C" void kernel_launch(void* const* d_in, const int* in_sizes, int n_in,
                              void* d_out, int out_size) {
    const float* A        = (const float*)d_in[0];  // encoder_word_embeds [B,S,E]
    const int*   lengths  = (const int*)d_in[1];    // encoder_lengths [B]
    const float* context  = (const float*)d_in[2];  // context_state [B,C]
    const float* W_word   = (const float*)d_in[3];  // [H,E]
    const float* b_word   = (const float*)d_in[4];  // [H]
    const float* W_ctx    = (const float*)d_in[5];  // [H,C]
    const float* b_ctx    = (const float*)d_in[6];  // [H]
    const float* w_hidden = (const float*)d_in[7];  // [H]

    float* out = (float*)d_out;
    float* feat_out = out;                                        // [B,E] first
    float* attn_out = (out_size >= B_ * E_ + B_ * S_) ? out + B_ * E_ : nullptr;  // [B,S] second

    ctx_kernel<<<B_, H_>>>(context, W_ctx, b_ctx, b_word);

    dim3 g2(S_ / 64, B_);
    scores_kernel<<<g2, 256>>>(A, W_word, lengths, w_hidden);

    attn_softmax_kernel<<<B_, 256>>>(lengths, attn_out);

    dim3 g4(8, B_);
    wsum_kernel<<<g4, 128>>>(A, lengths);

    reduce_kernel<<<B_, E_>>>(feat_out);
}

// round 11
// speedup vs baseline: 1.1878x; 1.1872x over previous
#include <cuda_runtime.h>
#include <mma.h>
#include <cstdint>
#include <cstddef>

using namespace nvcuda;

#define B_ 64
#define S_ 2048
#define E_ 512
#define C_ 512
#define H_ 256

// ---------------- scratch (static device globals; no allocation) ----------------
__device__ float g_ctx[B_ * H_];         // ctx_feat + b_ctx + b_word  [B,H]
__device__ float g_scores[B_ * S_];      // pre-softmax scores         [B,S]
__device__ float g_attn[B_ * S_];        // normalized attention       [B,S]
__device__ float g_part[16 * B_ * E_];   // weighted-sum partials      [16,B,E]

__device__ __forceinline__ uint32_t smem_u32(const void* p) {
    uint32_t a;
    asm("{ .reg .u64 t; cvta.to.shared.u64 t, %1; cvt.u32.u64 %0, t; }" : "=r"(a) : "l"(p));
    return a;
}

#define CP_ASYNC16(dst, src)                                                          \
    asm volatile("cp.async.cg.shared.global [%0], [%1], 16;" ::"r"(dst), "l"(src)     \
                 : "memory")
#define CP_COMMIT() asm volatile("cp.async.commit_group;" ::: "memory")
#define CP_WAIT1()  asm volatile("cp.async.wait_group 1;" ::: "memory")
#define CP_WAIT0()  asm volatile("cp.async.wait_group 0;" ::: "memory")

// ---------------------------------------------------------------------------
// Kernel 1: ctx_feat[b,h] = b_ctx[h] + b_word[h] + context[b,:] . W_ctx[h,:]
// ---------------------------------------------------------------------------
__global__ void ctx_kernel(const float* __restrict__ context,
                           const float* __restrict__ W_ctx,
                           const float* __restrict__ b_ctx,
                           const float* __restrict__ b_word) {
    int b = blockIdx.x, h = threadIdx.x;
    const float4* wr = reinterpret_cast<const float4*>(W_ctx + (size_t)h * C_);
    const float4* cr = reinterpret_cast<const float4*>(context + (size_t)b * C_);
    float acc = b_ctx[h] + b_word[h];
#pragma unroll 8
    for (int i = 0; i < C_ / 4; i++) {
        float4 w = wr[i];
        float4 c = cr[i];
        acc += w.x * c.x + w.y * c.y + w.z * c.z + w.w * c.w;
    }
    g_ctx[b * H_ + h] = acc;
}

// ---------------------------------------------------------------------------
// Kernel 2: scores = w_hidden . tanh(A@W_word^T + ctx), tf32 wmma (legacy HMMA;
// tcgen05 unavailable: harness PTX target is compute_103 without the 'a').
// CTA = 128 s-rows x 256 H-cols x K=512. 512 threads (16 warps: wm 0..3 x wn 0..3).
// cp.async double-buffered K=32 chunks: chunk k+1 streams while k computes.
// ---------------------------------------------------------------------------
#define LDAB 36   // smem leading dim, bank-staggered; 36*4=144B (16B multiple)
#define LDWF 132

#define A_FL (128 * LDAB)   // floats per A buffer
#define B_FL (256 * LDAB)   // floats per B buffer

__global__ __launch_bounds__(512, 1) void scores_kernel(
    const float* __restrict__ A,         // [B,S,E]
    const float* __restrict__ Ww,        // W_word [H,E]
    const int* __restrict__ lengths,
    const float* __restrict__ w_hidden) {
    int b = blockIdx.y;
    int s0 = blockIdx.x * 128;
    int len = lengths[b];
    if (s0 >= len) return;  // scores past length are never read

    extern __shared__ __align__(16) float smf[];
    float* As0 = smf;                    // [2][128*LDAB]
    float* Bs0 = smf + 2 * A_FL;         // [2][256*LDAB]
    float* ctx_s = smf + 2 * A_FL + 2 * B_FL;  // 256
    float* wh_s = ctx_s + 256;                  // 256
    // epilogue word_feat buffer reuses smf[0 .. 128*LDWF) (post-GEMM)

    int tid = threadIdx.x;
    int lane = tid & 31, wid = tid >> 5;
    int wm = wid & 3, wn = wid >> 2;

    if (tid < 256) {
        ctx_s[tid] = g_ctx[b * H_ + tid];
        wh_s[tid] = w_hidden[tid];
    }

    wmma::fragment<wmma::accumulator, 16, 16, 8, float> acc[2][4];
#pragma unroll
    for (int mi = 0; mi < 2; mi++)
#pragma unroll
        for (int ni = 0; ni < 4; ni++) wmma::fill_fragment(acc[mi][ni], 0.0f);

    const float* Ab = A + ((size_t)b * S_ + s0) * E_;
    uint32_t As_u = smem_u32(As0);
    uint32_t Bs_u = smem_u32(Bs0);

    // ---- async stage of one K=32 chunk into buffer `buf` ----
    auto load_chunk = [&](int kc, int buf) {
        int k0 = kc * 32;
        uint32_t ab = As_u + (uint32_t)buf * A_FL * 4u;
        uint32_t bb = Bs_u + (uint32_t)buf * B_FL * 4u;
#pragma unroll
        for (int i = 0; i < 2; i++) {  // A: 128x32 = 1024 float4
            int idx = tid + i * 512;
            int r = idx >> 3, c4 = (idx & 7) * 4;
            CP_ASYNC16(ab + (uint32_t)(r * LDAB + c4) * 4u,
                       Ab + (size_t)r * E_ + k0 + c4);
        }
#pragma unroll
        for (int i = 0; i < 4; i++) {  // B: 256x32 = 2048 float4
            int idx = tid + i * 512;
            int h = idx >> 3, c4 = (idx & 7) * 4;
            CP_ASYNC16(bb + (uint32_t)(h * LDAB + c4) * 4u,
                       Ww + (size_t)h * E_ + k0 + c4);
        }
    };

    load_chunk(0, 0);
    CP_COMMIT();

    for (int kc = 0; kc < 16; kc++) {
        int buf = kc & 1;
        if (kc + 1 < 16) {
            load_chunk(kc + 1, buf ^ 1);
            CP_COMMIT();
            CP_WAIT1();  // chunk kc has landed; kc+1 still in flight
        } else {
            CP_WAIT0();
        }
        __syncthreads();

        const float* As = As0 + buf * A_FL;
        const float* Bs = Bs0 + buf * B_FL;
#pragma unroll
        for (int kk = 0; kk < 4; kk++) {
            int ko = kk * 8;
            wmma::fragment<wmma::matrix_a, 16, 16, 8, wmma::precision::tf32,
                           wmma::row_major> af[2];
            wmma::fragment<wmma::matrix_b, 16, 16, 8, wmma::precision::tf32,
                           wmma::col_major> bf[4];
            wmma::load_matrix_sync(af[0], As + (wm * 32) * LDAB + ko, LDAB);
            wmma::load_matrix_sync(af[1], As + (wm * 32 + 16) * LDAB + ko, LDAB);
#pragma unroll
            for (int ni = 0; ni < 4; ni++)
                wmma::load_matrix_sync(bf[ni], Bs + (wn * 64 + ni * 16) * LDAB + ko, LDAB);
#pragma unroll
            for (int mi = 0; mi < 2; mi++)
#pragma unroll
                for (int ni = 0; ni < 4; ni++)
                    wmma::mma_sync(acc[mi][ni], af[mi], bf[ni], acc[mi][ni]);
        }
        __syncthreads();  // all warps done reading buf before it is refilled
    }

    // ---- epilogue: two column-halves via smem, tanh + dot(w_hidden) ----
    float psum[8];
#pragma unroll
    for (int rr = 0; rr < 8; rr++) psum[rr] = 0.0f;

#pragma unroll
    for (int hh = 0; hh < 2; hh++) {
        __syncthreads();
        if ((wn >> 1) == hh) {
            int cw = (wn & 1) * 64;
#pragma unroll
            for (int mi = 0; mi < 2; mi++)
#pragma unroll
                for (int ni = 0; ni < 4; ni++)
                    wmma::store_matrix_sync(
                        smf + (wm * 32 + mi * 16) * LDWF + cw + ni * 16,
                        acc[mi][ni], LDWF, wmma::mem_row_major);
        }
        __syncthreads();
#pragma unroll
        for (int rr = 0; rr < 8; rr++) {
            int r = wid * 8 + rr;
#pragma unroll
            for (int j = 0; j < 4; j++) {
                int c = lane + j * 32;
                float x = smf[r * LDWF + c] + ctx_s[hh * 128 + c];
                x = fminf(fmaxf(x, -15.0f), 15.0f);
                float e2 = __expf(2.0f * x);
                psum[rr] += __fdividef(e2 - 1.0f, e2 + 1.0f) * wh_s[hh * 128 + c];
            }
        }
    }
#pragma unroll
    for (int rr = 0; rr < 8; rr++) {
        float s = psum[rr];
#pragma unroll
        for (int o = 16; o > 0; o >>= 1) s += __shfl_xor_sync(0xffffffffu, s, o);
        if (lane == 0) g_scores[(size_t)b * S_ + s0 + wid * 8 + rr] = s;
    }
}

// ---------------------------------------------------------------------------
// Kernel 3: masked softmax (exact: exp(s-m)/L on valid prefix)
// ---------------------------------------------------------------------------
__global__ __launch_bounds__(256) void attn_softmax_kernel(const int* __restrict__ lengths,
                                                           float* __restrict__ attn_out) {
    int b = blockIdx.x, tid = threadIdx.x;
    int lane = tid & 31, wid = tid >> 5;
    int len = lengths[b];
    const float* sc = g_scores + (size_t)b * S_;

    float v[8];
    float m = -1e30f;
#pragma unroll
    for (int i = 0; i < 8; i++) {
        int s = tid + i * 256;
        v[i] = (s < len) ? sc[s] : -1e30f;
        m = fmaxf(m, v[i]);
    }
#pragma unroll
    for (int o = 16; o > 0; o >>= 1) m = fmaxf(m, __shfl_xor_sync(0xffffffffu, m, o));
    __shared__ float red[8];
    if (lane == 0) red[wid] = m;
    __syncthreads();
    float mm = red[0];
#pragma unroll
    for (int i = 1; i < 8; i++) mm = fmaxf(mm, red[i]);

    float t[8];
    float L = 0.0f;
#pragma unroll
    for (int i = 0; i < 8; i++) {
        int s = tid + i * 256;
        t[i] = (s < len) ? __expf(v[i] - mm) : 0.0f;
        L += t[i];
    }
#pragma unroll
    for (int o = 16; o > 0; o >>= 1) L += __shfl_xor_sync(0xffffffffu, L, o);
    __syncthreads();
    if (lane == 0) red[wid] = L;
    __syncthreads();
    float Lt = 0.0f;
#pragma unroll
    for (int i = 0; i < 8; i++) Lt += red[i];
    float inv = __fdividef(1.0f, Lt);

#pragma unroll
    for (int i = 0; i < 8; i++) {
        int s = tid + i * 256;
        float a = t[i] * inv;
        g_attn[(size_t)b * S_ + s] = a;
        if (attn_out) attn_out[(size_t)b * S_ + s] = a;
    }
}

// ---------------------------------------------------------------------------
// Kernel 4: weighted-sum partials. grid (16, B): s-chunks of 128, 4-way unroll.
// ---------------------------------------------------------------------------
__global__ __launch_bounds__(128) void wsum_kernel(const float* __restrict__ A,
                                                   const int* __restrict__ lengths) {
    int q = blockIdx.x, b = blockIdx.y;
    int tid = threadIdx.x;
    int len = lengths[b];
    int nv = len - q * 128;
    nv = (nv > 128) ? 128 : nv;

    float4 acc0 = make_float4(0.f, 0.f, 0.f, 0.f);
    float4 acc1 = make_float4(0.f, 0.f, 0.f, 0.f);
    if (nv > 0) {
        const float* Ab = A + ((size_t)b * S_ + q * 128) * E_ + tid * 4;
        const float* at = g_attn + (size_t)b * S_ + q * 128;
        int s = 0;
        for (; s + 4 <= nv; s += 4) {
            float w0 = at[s], w1 = at[s + 1], w2 = at[s + 2], w3 = at[s + 3];
            float4 a0 = *reinterpret_cast<const float4*>(Ab + (size_t)s * E_);
            float4 a1 = *reinterpret_cast<const float4*>(Ab + (size_t)(s + 1) * E_);
            float4 a2 = *reinterpret_cast<const float4*>(Ab + (size_t)(s + 2) * E_);
            float4 a3 = *reinterpret_cast<const float4*>(Ab + (size_t)(s + 3) * E_);
            acc0.x += w0 * a0.x + w2 * a2.x;
            acc0.y += w0 * a0.y + w2 * a2.y;
            acc0.z += w0 * a0.z + w2 * a2.z;
            acc0.w += w0 * a0.w + w2 * a2.w;
            acc1.x += w1 * a1.x + w3 * a3.x;
            acc1.y += w1 * a1.y + w3 * a3.y;
            acc1.z += w1 * a1.z + w3 * a3.z;
            acc1.w += w1 * a1.w + w3 * a3.w;
        }
        for (; s < nv; s++) {
            float w = at[s];
            float4 a = *reinterpret_cast<const float4*>(Ab + (size_t)s * E_);
            acc0.x += w * a.x; acc0.y += w * a.y; acc0.z += w * a.z; acc0.w += w * a.w;
        }
    }
    acc0.x += acc1.x; acc0.y += acc1.y; acc0.z += acc1.z; acc0.w += acc1.w;
    *reinterpret_cast<float4*>(g_part + ((size_t)(q * B_ + b)) * E_ + tid * 4) = acc0;
}

// ---------------------------------------------------------------------------
// Kernel 5: reduce 16 partials -> attention_features
// ---------------------------------------------------------------------------
__global__ void reduce_kernel(float* __restrict__ feat) {
    int b = blockIdx.x, e = threadIdx.x;
    float s = 0.0f;
#pragma unroll
    for (int q = 0; q < 16; q++) s += g_part[((size_t)(q * B_ + b)) * E_ + e];
    feat[b * E_ + e] = s;
}

// ---------------------------------------------------------------------------
extern "C" void kernel_launch(void* const* d_in, const int* in_sizes, int n_in,
                              void* d_out, int out_size) {
    const float* A        = (const float*)d_in[0];
    const int*   lengths  = (const int*)d_in[1];
    const float* context  = (const float*)d_in[2];
    const float* W_word   = (const float*)d_in[3];
    const float* b_word   = (const float*)d_in[4];
    const float* W_ctx    = (const float*)d_in[5];
    const float* b_ctx    = (const float*)d_in[6];
    const float* w_hidden = (const float*)d_in[7];

    float* out = (float*)d_out;
    float* feat_out = out;
    float* attn_out = (out_size >= B_ * E_ + B_ * S_) ? out + B_ * E_ : nullptr;

    // smem: 2*A(18432B) + 2*B(36864B) + ctx/wh(2048B) = 112640 B
    const int SCORES_SMEM = (2 * A_FL + 2 * B_FL + 512) * 4;
    cudaFuncSetAttribute(scores_kernel, cudaFuncAttributeMaxDynamicSharedMemorySize,
                         SCORES_SMEM);

    ctx_kernel<<<B_, H_>>>(context, W_ctx, b_ctx, b_word);

    dim3 g2(S_ / 128, B_);
    scores_kernel<<<g2, 512, SCORES_SMEM>>>(A, W_word, lengths, w_hidden);

    attn_softmax_kernel<<<B_, 256>>>(lengths, attn_out);

    dim3 g4(16, B_);
    wsum_kernel<<<g4, 128>>>(A, lengths);

    reduce_kernel<<<B_, E_>>>(feat_out);
}

// round 12
// speedup vs baseline: 1.1895x; 1.0014x over previous
#include <cuda_runtime.h>
#include <mma.h>
#include <cstdint>
#include <cstddef>

using namespace nvcuda;

#define B_ 64
#define S_ 2048
#define E_ 512
#define C_ 512
#define H_ 256

// ---------------- scratch (static device globals; no allocation) ----------------
__device__ float g_ctx[B_ * H_];         // ctx_feat + b_ctx + b_word  [B,H]
__device__ float g_scores[B_ * S_];      // pre-softmax scores         [B,S]
__device__ float g_attn[B_ * S_];        // normalized attention       [B,S]
__device__ float g_part[16 * B_ * E_];   // weighted-sum partials      [16,B,E]

__device__ __forceinline__ uint32_t smem_u32(const void* p) {
    uint32_t a;
    asm("{ .reg .u64 t; cvta.to.shared.u64 t, %1; cvt.u32.u64 %0, t; }" : "=r"(a) : "l"(p));
    return a;
}

#define CP_ASYNC16(dst, src)                                                          \
    asm volatile("cp.async.cg.shared.global [%0], [%1], 16;" ::"r"(dst), "l"(src)     \
                 : "memory")
#define CP_COMMIT() asm volatile("cp.async.commit_group;" ::: "memory")
#define CP_WAIT1()  asm volatile("cp.async.wait_group 1;" ::: "memory")
#define CP_WAIT0()  asm volatile("cp.async.wait_group 0;" ::: "memory")

// ---------------------------------------------------------------------------
// Kernel 1: ctx_feat[b,h] = b_ctx[h] + b_word[h] + context[b,:] . W_ctx[h,:]
// ---------------------------------------------------------------------------
__global__ void ctx_kernel(const float* __restrict__ context,
                           const float* __restrict__ W_ctx,
                           const float* __restrict__ b_ctx,
                           const float* __restrict__ b_word) {
    int b = blockIdx.x, h = threadIdx.x;
    const float4* wr = reinterpret_cast<const float4*>(W_ctx + (size_t)h * C_);
    const float4* cr = reinterpret_cast<const float4*>(context + (size_t)b * C_);
    float acc = b_ctx[h] + b_word[h];
#pragma unroll 8
    for (int i = 0; i < C_ / 4; i++) {
        float4 w = wr[i];
        float4 c = cr[i];
        acc += w.x * c.x + w.y * c.y + w.z * c.z + w.w * c.w;
    }
    g_ctx[b * H_ + h] = acc;
}

// ---------------------------------------------------------------------------
// Kernel 2: scores = w_hidden . tanh(A@W_word^T + ctx), tf32 wmma (legacy HMMA;
// tcgen05 unavailable: harness PTX target is compute_103 without the 'a').
// CTA = 128 s-rows x 256 H-cols x K=512. 512 threads (16 warps: wm 0..3 x wn 0..3).
// cp.async double-buffered K=32 chunks: chunk k+1 streams while k computes.
// ---------------------------------------------------------------------------
#define LDAB 36   // smem leading dim, bank-staggered; 36*4=144B (16B multiple)
#define LDWF 132

#define A_FL (128 * LDAB)   // floats per A buffer
#define B_FL (256 * LDAB)   // floats per B buffer

__global__ __launch_bounds__(512, 1) void scores_kernel(
    const float* __restrict__ A,         // [B,S,E]
    const float* __restrict__ Ww,        // W_word [H,E]
    const int* __restrict__ lengths,
    const float* __restrict__ w_hidden) {
    int b = blockIdx.y;
    int s0 = blockIdx.x * 128;
    int len = lengths[b];
    if (s0 >= len) return;  // scores past length are never read

    extern __shared__ __align__(16) float smf[];
    float* As0 = smf;                    // [2][128*LDAB]
    float* Bs0 = smf + 2 * A_FL;         // [2][256*LDAB]
    float* ctx_s = smf + 2 * A_FL + 2 * B_FL;  // 256
    float* wh_s = ctx_s + 256;                  // 256
    // epilogue word_feat buffer reuses smf[0 .. 128*LDWF) (post-GEMM)

    int tid = threadIdx.x;
    int lane = tid & 31, wid = tid >> 5;
    int wm = wid & 3, wn = wid >> 2;

    if (tid < 256) {
        ctx_s[tid] = g_ctx[b * H_ + tid];
        wh_s[tid] = w_hidden[tid];
    }

    wmma::fragment<wmma::accumulator, 16, 16, 8, float> acc[2][4];
#pragma unroll
    for (int mi = 0; mi < 2; mi++)
#pragma unroll
        for (int ni = 0; ni < 4; ni++) wmma::fill_fragment(acc[mi][ni], 0.0f);

    const float* Ab = A + ((size_t)b * S_ + s0) * E_;
    uint32_t As_u = smem_u32(As0);
    uint32_t Bs_u = smem_u32(Bs0);

    // ---- async stage of one K=32 chunk into buffer `buf` ----
    auto load_chunk = [&](int kc, int buf) {
        int k0 = kc * 32;
        uint32_t ab = As_u + (uint32_t)buf * A_FL * 4u;
        uint32_t bb = Bs_u + (uint32_t)buf * B_FL * 4u;
#pragma unroll
        for (int i = 0; i < 2; i++) {  // A: 128x32 = 1024 float4
            int idx = tid + i * 512;
            int r = idx >> 3, c4 = (idx & 7) * 4;
            CP_ASYNC16(ab + (uint32_t)(r * LDAB + c4) * 4u,
                       Ab + (size_t)r * E_ + k0 + c4);
        }
#pragma unroll
        for (int i = 0; i < 4; i++) {  // B: 256x32 = 2048 float4
            int idx = tid + i * 512;
            int h = idx >> 3, c4 = (idx & 7) * 4;
            CP_ASYNC16(bb + (uint32_t)(h * LDAB + c4) * 4u,
                       Ww + (size_t)h * E_ + k0 + c4);
        }
    };

    load_chunk(0, 0);
    CP_COMMIT();

    for (int kc = 0; kc < 16; kc++) {
        int buf = kc & 1;
        if (kc + 1 < 16) {
            load_chunk(kc + 1, buf ^ 1);
            CP_COMMIT();
            CP_WAIT1();  // chunk kc has landed; kc+1 still in flight
        } else {
            CP_WAIT0();
        }
        __syncthreads();

        const float* As = As0 + buf * A_FL;
        const float* Bs = Bs0 + buf * B_FL;
#pragma unroll
        for (int kk = 0; kk < 4; kk++) {
            int ko = kk * 8;
            wmma::fragment<wmma::matrix_a, 16, 16, 8, wmma::precision::tf32,
                           wmma::row_major> af[2];
            wmma::fragment<wmma::matrix_b, 16, 16, 8, wmma::precision::tf32,
                           wmma::col_major> bf[4];
            wmma::load_matrix_sync(af[0], As + (wm * 32) * LDAB + ko, LDAB);
            wmma::load_matrix_sync(af[1], As + (wm * 32 + 16) * LDAB + ko, LDAB);
#pragma unroll
            for (int ni = 0; ni < 4; ni++)
                wmma::load_matrix_sync(bf[ni], Bs + (wn * 64 + ni * 16) * LDAB + ko, LDAB);
#pragma unroll
            for (int mi = 0; mi < 2; mi++)
#pragma unroll
                for (int ni = 0; ni < 4; ni++)
                    wmma::mma_sync(acc[mi][ni], af[mi], bf[ni], acc[mi][ni]);
        }
        __syncthreads();  // all warps done reading buf before it is refilled
    }

    // ---- epilogue: two column-halves via smem, tanh + dot(w_hidden) ----
    float psum[8];
#pragma unroll
    for (int rr = 0; rr < 8; rr++) psum[rr] = 0.0f;

#pragma unroll
    for (int hh = 0; hh < 2; hh++) {
        __syncthreads();
        if ((wn >> 1) == hh) {
            int cw = (wn & 1) * 64;
#pragma unroll
            for (int mi = 0; mi < 2; mi++)
#pragma unroll
                for (int ni = 0; ni < 4; ni++)
                    wmma::store_matrix_sync(
                        smf + (wm * 32 + mi * 16) * LDWF + cw + ni * 16,
                        acc[mi][ni], LDWF, wmma::mem_row_major);
        }
        __syncthreads();
#pragma unroll
        for (int rr = 0; rr < 8; rr++) {
            int r = wid * 8 + rr;
#pragma unroll
            for (int j = 0; j < 4; j++) {
                int c = lane + j * 32;
                float x = smf[r * LDWF + c] + ctx_s[hh * 128 + c];
                x = fminf(fmaxf(x, -15.0f), 15.0f);
                float e2 = __expf(2.0f * x);
                psum[rr] += __fdividef(e2 - 1.0f, e2 + 1.0f) * wh_s[hh * 128 + c];
            }
        }
    }
#pragma unroll
    for (int rr = 0; rr < 8; rr++) {
        float s = psum[rr];
#pragma unroll
        for (int o = 16; o > 0; o >>= 1) s += __shfl_xor_sync(0xffffffffu, s, o);
        if (lane == 0) g_scores[(size_t)b * S_ + s0 + wid * 8 + rr] = s;
    }
}

// ---------------------------------------------------------------------------
// Kernel 3: masked softmax (exact: exp(s-m)/L on valid prefix)
// ---------------------------------------------------------------------------
__global__ __launch_bounds__(256) void attn_softmax_kernel(const int* __restrict__ lengths,
                                                           float* __restrict__ attn_out) {
    int b = blockIdx.x, tid = threadIdx.x;
    int lane = tid & 31, wid = tid >> 5;
    int len = lengths[b];
    const float* sc = g_scores + (size_t)b * S_;

    float v[8];
    float m = -1e30f;
#pragma unroll
    for (int i = 0; i < 8; i++) {
        int s = tid + i * 256;
        v[i] = (s < len) ? sc[s] : -1e30f;
        m = fmaxf(m, v[i]);
    }
#pragma unroll
    for (int o = 16; o > 0; o >>= 1) m = fmaxf(m, __shfl_xor_sync(0xffffffffu, m, o));
    __shared__ float red[8];
    if (lane == 0) red[wid] = m;
    __syncthreads();
    float mm = red[0];
#pragma unroll
    for (int i = 1; i < 8; i++) mm = fmaxf(mm, red[i]);

    float t[8];
    float L = 0.0f;
#pragma unroll
    for (int i = 0; i < 8; i++) {
        int s = tid + i * 256;
        t[i] = (s < len) ? __expf(v[i] - mm) : 0.0f;
        L += t[i];
    }
#pragma unroll
    for (int o = 16; o > 0; o >>= 1) L += __shfl_xor_sync(0xffffffffu, L, o);
    __syncthreads();
    if (lane == 0) red[wid] = L;
    __syncthreads();
    float Lt = 0.0f;
#pragma unroll
    for (int i = 0; i < 8; i++) Lt += red[i];
    float inv = __fdividef(1.0f, Lt);

#pragma unroll
    for (int i = 0; i < 8; i++) {
        int s = tid + i * 256;
        float a = t[i] * inv;
        g_attn[(size_t)b * S_ + s] = a;
        if (attn_out) attn_out[(size_t)b * S_ + s] = a;
    }
}

// ---------------------------------------------------------------------------
// Kernel 4: weighted-sum partials. grid (16, B): s-chunks of 128, 4-way unroll.
// ---------------------------------------------------------------------------
__global__ __launch_bounds__(128) void wsum_kernel(const float* __restrict__ A,
                                                   const int* __restrict__ lengths) {
    int q = blockIdx.x, b = blockIdx.y;
    int tid = threadIdx.x;
    int len = lengths[b];
    int nv = len - q * 128;
    nv = (nv > 128) ? 128 : nv;

    float4 acc0 = make_float4(0.f, 0.f, 0.f, 0.f);
    float4 acc1 = make_float4(0.f, 0.f, 0.f, 0.f);
    if (nv > 0) {
        const float* Ab = A + ((size_t)b * S_ + q * 128) * E_ + tid * 4;
        const float* at = g_attn + (size_t)b * S_ + q * 128;
        int s = 0;
        for (; s + 4 <= nv; s += 4) {
            float w0 = at[s], w1 = at[s + 1], w2 = at[s + 2], w3 = at[s + 3];
            float4 a0 = *reinterpret_cast<const float4*>(Ab + (size_t)s * E_);
            float4 a1 = *reinterpret_cast<const float4*>(Ab + (size_t)(s + 1) * E_);
            float4 a2 = *reinterpret_cast<const float4*>(Ab + (size_t)(s + 2) * E_);
            float4 a3 = *reinterpret_cast<const float4*>(Ab + (size_t)(s + 3) * E_);
            acc0.x += w0 * a0.x + w2 * a2.x;
            acc0.y += w0 * a0.y + w2 * a2.y;
            acc0.z += w0 * a0.z + w2 * a2.z;
            acc0.w += w0 * a0.w + w2 * a2.w;
            acc1.x += w1 * a1.x + w3 * a3.x;
            acc1.y += w1 * a1.y + w3 * a3.y;
            acc1.z += w1 * a1.z + w3 * a3.z;
            acc1.w += w1 * a1.w + w3 * a3.w;
        }
        for (; s < nv; s++) {
            float w = at[s];
            float4 a = *reinterpret_cast<const float4*>(Ab + (size_t)s * E_);
            acc0.x += w * a.x; acc0.y += w * a.y; acc0.z += w * a.z; acc0.w += w * a.w;
        }
    }
    acc0.x += acc1.x; acc0.y += acc1.y; acc0.z += acc1.z; acc0.w += acc1.w;
    *reinterpret_cast<float4*>(g_part + ((size_t)(q * B_ + b)) * E_ + tid * 4) = acc0;
}

// ---------------------------------------------------------------------------
// Kernel 5: reduce 16 partials -> attention_features
// ---------------------------------------------------------------------------
__global__ void reduce_kernel(float* __restrict__ feat) {
    int b = blockIdx.x, e = threadIdx.x;
    float s = 0.0f;
#pragma unroll
    for (int q = 0; q < 16; q++) s += g_part[((size_t)(q * B_ + b)) * E_ + e];
    feat[b * E_ + e] = s;
}

// ---------------------------------------------------------------------------
extern "C" void kernel_launch(void* const* d_in, const int* in_sizes, int n_in,
                              void* d_out, int out_size) {
    const float* A        = (const float*)d_in[0];
    const int*   lengths  = (const int*)d_in[1];
    const float* context  = (const float*)d_in[2];
    const float* W_word   = (const float*)d_in[3];
    const float* b_word   = (const float*)d_in[4];
    const float* W_ctx    = (const float*)d_in[5];
    const float* b_ctx    = (const float*)d_in[6];
    const float* w_hidden = (const float*)d_in[7];

    float* out = (float*)d_out;
    float* feat_out = out;
    float* attn_out = (out_size >= B_ * E_ + B_ * S_) ? out + B_ * E_ : nullptr;

    // smem: 2*A(18432B) + 2*B(36864B) + ctx/wh(2048B) = 112640 B
    const int SCORES_SMEM = (2 * A_FL + 2 * B_FL + 512) * 4;
    cudaFuncSetAttribute(scores_kernel, cudaFuncAttributeMaxDynamicSharedMemorySize,
                         SCORES_SMEM);

    ctx_kernel<<<B_, H_>>>(context, W_ctx, b_ctx, b_word);

    dim3 g2(S_ / 128, B_);
    scores_kernel<<<g2, 512, SCORES_SMEM>>>(A, W_word, lengths, w_hidden);

    attn_softmax_kernel<<<B_, 256>>>(lengths, attn_out);

    dim3 g4(16, B_);
    wsum_kernel<<<g4, 128>>>(A, lengths);

    reduce_kernel<<<B_, E_>>>(feat_out);
}

// round 13
// speedup vs baseline: 2.8039x; 2.3572x over previous
#include <cuda_runtime.h>
#include <cuda_fp16.h>
#include <mma.h>
#include <cstdint>
#include <cstddef>

using namespace nvcuda;

#define B_ 64
#define S_ 2048
#define E_ 512
#define C_ 512
#define H_ 256

// ---------------- scratch (static device globals; no allocation) ----------------
__device__ float g_ctx[B_ * H_];         // ctx_feat + b_ctx + b_word  [B,H]
__device__ float g_scores[B_ * S_];      // pre-softmax scores         [B,S]
__device__ float g_attn[B_ * S_];        // normalized attention       [B,S]
__device__ float g_part[32 * B_ * E_];   // weighted-sum partials      [32,B,E]

// ---------------------------------------------------------------------------
// Kernel 1: ctx_feat[b,h] = b_ctx[h] + b_word[h] + context[b,:] . W_ctx[h,:]
// ---------------------------------------------------------------------------
__global__ void ctx_kernel(const float* __restrict__ context,
                           const float* __restrict__ W_ctx,
                           const float* __restrict__ b_ctx,
                           const float* __restrict__ b_word) {
    int b = blockIdx.x, h = threadIdx.x;
    const float4* wr = reinterpret_cast<const float4*>(W_ctx + (size_t)h * C_);
    const float4* cr = reinterpret_cast<const float4*>(context + (size_t)b * C_);
    float acc = b_ctx[h] + b_word[h];
#pragma unroll 8
    for (int i = 0; i < C_ / 4; i++) {
        float4 w = wr[i];
        float4 c = cr[i];
        acc += w.x * c.x + w.y * c.y + w.z * c.z + w.w * c.w;
    }
    g_ctx[b * H_ + h] = acc;
}

// ---------------------------------------------------------------------------
// Kernel 2: scores = w_hidden . tanh(A@W_word^T + ctx), fp16 wmma m16n16k16.
// fp16 RN has the same 10-bit mantissa as tf32 but K=16/instr vs K=8 -> half
// the HMMA instructions (legacy pipe is instruction-issue bound).
// CTA = 128 s-rows x 256 H-cols x K=512, 512 threads (16 warps, wm0..3 x wn0..3).
// Register-prefetched LDG -> cvt.f16 -> STS double-buffered K=32 chunks.
// ---------------------------------------------------------------------------
#define LDH 40                 // smem leading dim in halves (80B, 16B multiple)
#define A_HL (128 * LDH)       // halves per A buffer (5120)
#define B_HL (256 * LDH)       // halves per B buffer (10240)
#define LDWF 132

__global__ __launch_bounds__(512, 1) void scores_kernel(
    const float* __restrict__ A,         // [B,S,E]
    const float* __restrict__ Ww,        // W_word [H,E]
    const int* __restrict__ lengths,
    const float* __restrict__ w_hidden) {
    int b = blockIdx.y;
    int s0 = blockIdx.x * 128;
    int len = lengths[b];
    if (s0 >= len) return;  // scores past length are never read

    extern __shared__ __align__(128) char smc[];
    __half* As0 = reinterpret_cast<__half*>(smc);             // [2][A_HL]
    __half* Bs0 = reinterpret_cast<__half*>(smc + 2 * A_HL * 2);  // [2][B_HL]
    float* epif = reinterpret_cast<float*>(smc);              // epilogue 128xLDWF
    float* ctx_s = reinterpret_cast<float*>(smc + 128 * LDWF * 4);
    float* wh_s = ctx_s + 256;

    int tid = threadIdx.x;
    int lane = tid & 31, wid = tid >> 5;
    int wm = wid & 3, wn = wid >> 2;

    if (tid < 256) {
        ctx_s[tid] = g_ctx[b * H_ + tid];
        wh_s[tid] = w_hidden[tid];
    }

    wmma::fragment<wmma::accumulator, 16, 16, 16, float> acc[2][4];
#pragma unroll
    for (int mi = 0; mi < 2; mi++)
#pragma unroll
        for (int ni = 0; ni < 4; ni++) wmma::fill_fragment(acc[mi][ni], 0.0f);

    const float* Ab = A + ((size_t)b * S_ + s0) * E_;

    // per-thread staging slots (K=32 chunk): A 2 x float4, B 4 x float4
    int ar[2], ac[2], br[4], bc[4];
#pragma unroll
    for (int i = 0; i < 2; i++) {
        int idx = tid + i * 512;
        ar[i] = idx >> 3;
        ac[i] = (idx & 7) * 4;
    }
#pragma unroll
    for (int i = 0; i < 4; i++) {
        int idx = tid + i * 512;
        br[i] = idx >> 3;
        bc[i] = (idx & 7) * 4;
    }

    float4 ra[2], rb[4];
    // prefetch chunk 0
#pragma unroll
    for (int i = 0; i < 2; i++)
        ra[i] = *reinterpret_cast<const float4*>(Ab + (size_t)ar[i] * E_ + ac[i]);
#pragma unroll
    for (int i = 0; i < 4; i++)
        rb[i] = *reinterpret_cast<const float4*>(Ww + (size_t)br[i] * E_ + bc[i]);

    for (int kc = 0; kc < 16; kc++) {
        int buf = kc & 1;
        __half* Asb = As0 + buf * A_HL;
        __half* Bsb = Bs0 + buf * B_HL;
        // convert + store chunk kc (writes buf; other warps may still mma on buf^1)
#pragma unroll
        for (int i = 0; i < 2; i++) {
            __half2 p0 = __floats2half2_rn(ra[i].x, ra[i].y);
            __half2 p1 = __floats2half2_rn(ra[i].z, ra[i].w);
            uint2 u = make_uint2(*reinterpret_cast<uint32_t*>(&p0),
                                 *reinterpret_cast<uint32_t*>(&p1));
            *reinterpret_cast<uint2*>(&Asb[ar[i] * LDH + ac[i]]) = u;
        }
#pragma unroll
        for (int i = 0; i < 4; i++) {
            __half2 p0 = __floats2half2_rn(rb[i].x, rb[i].y);
            __half2 p1 = __floats2half2_rn(rb[i].z, rb[i].w);
            uint2 u = make_uint2(*reinterpret_cast<uint32_t*>(&p0),
                                 *reinterpret_cast<uint32_t*>(&p1));
            *reinterpret_cast<uint2*>(&Bsb[br[i] * LDH + bc[i]]) = u;
        }
        __syncthreads();
        // prefetch chunk kc+1 (latency hides under the mma below)
        if (kc + 1 < 16) {
            int k0 = (kc + 1) * 32;
#pragma unroll
            for (int i = 0; i < 2; i++)
                ra[i] = *reinterpret_cast<const float4*>(Ab + (size_t)ar[i] * E_ + k0 + ac[i]);
#pragma unroll
            for (int i = 0; i < 4; i++)
                rb[i] = *reinterpret_cast<const float4*>(Ww + (size_t)br[i] * E_ + k0 + bc[i]);
        }
        const __half* As = As0 + buf * A_HL;
        const __half* Bs = Bs0 + buf * B_HL;
#pragma unroll
        for (int kk = 0; kk < 2; kk++) {
            int ko = kk * 16;
            wmma::fragment<wmma::matrix_a, 16, 16, 16, __half, wmma::row_major> af[2];
            wmma::load_matrix_sync(af[0], As + (wm * 32) * LDH + ko, LDH);
            wmma::load_matrix_sync(af[1], As + (wm * 32 + 16) * LDH + ko, LDH);
#pragma unroll
            for (int ni = 0; ni < 4; ni++) {
                wmma::fragment<wmma::matrix_b, 16, 16, 16, __half, wmma::col_major> bf;
                wmma::load_matrix_sync(bf, Bs + (wn * 64 + ni * 16) * LDH + ko, LDH);
                wmma::mma_sync(acc[0][ni], af[0], bf, acc[0][ni]);
                wmma::mma_sync(acc[1][ni], af[1], bf, acc[1][ni]);
            }
        }
        // no trailing sync: next iteration writes buf^1, which every warp already
        // finished reading before the sync above (mma(kc-1) precedes STS(kc)).
    }

    // ---- epilogue: two column-halves via smem, tanh + dot(w_hidden) ----
    float psum[8];
#pragma unroll
    for (int rr = 0; rr < 8; rr++) psum[rr] = 0.0f;

#pragma unroll
    for (int hh = 0; hh < 2; hh++) {
        __syncthreads();
        if ((wn >> 1) == hh) {
            int cw = (wn & 1) * 64;
#pragma unroll
            for (int mi = 0; mi < 2; mi++)
#pragma unroll
                for (int ni = 0; ni < 4; ni++)
                    wmma::store_matrix_sync(
                        epif + (wm * 32 + mi * 16) * LDWF + cw + ni * 16,
                        acc[mi][ni], LDWF, wmma::mem_row_major);
        }
        __syncthreads();
#pragma unroll
        for (int rr = 0; rr < 8; rr++) {
            int r = wid * 8 + rr;
#pragma unroll
            for (int j = 0; j < 4; j++) {
                int c = lane + j * 32;
                float x = epif[r * LDWF + c] + ctx_s[hh * 128 + c];
                x = fminf(fmaxf(x, -15.0f), 15.0f);
                float e2 = __expf(2.0f * x);
                psum[rr] += __fdividef(e2 - 1.0f, e2 + 1.0f) * wh_s[hh * 128 + c];
            }
        }
    }
#pragma unroll
    for (int rr = 0; rr < 8; rr++) {
        float s = psum[rr];
#pragma unroll
        for (int o = 16; o > 0; o >>= 1) s += __shfl_xor_sync(0xffffffffu, s, o);
        if (lane == 0) g_scores[(size_t)b * S_ + s0 + wid * 8 + rr] = s;
    }
}

// ---------------------------------------------------------------------------
// Kernel 3: masked softmax (exact: exp(s-m)/L on valid prefix)
// ---------------------------------------------------------------------------
__global__ __launch_bounds__(256) void attn_softmax_kernel(const int* __restrict__ lengths,
                                                           float* __restrict__ attn_out) {
    int b = blockIdx.x, tid = threadIdx.x;
    int lane = tid & 31, wid = tid >> 5;
    int len = lengths[b];
    const float* sc = g_scores + (size_t)b * S_;

    float v[8];
    float m = -1e30f;
#pragma unroll
    for (int i = 0; i < 8; i++) {
        int s = tid + i * 256;
        v[i] = (s < len) ? sc[s] : -1e30f;
        m = fmaxf(m, v[i]);
    }
#pragma unroll
    for (int o = 16; o > 0; o >>= 1) m = fmaxf(m, __shfl_xor_sync(0xffffffffu, m, o));
    __shared__ float red[8];
    if (lane == 0) red[wid] = m;
    __syncthreads();
    float mm = red[0];
#pragma unroll
    for (int i = 1; i < 8; i++) mm = fmaxf(mm, red[i]);

    float t[8];
    float L = 0.0f;
#pragma unroll
    for (int i = 0; i < 8; i++) {
        int s = tid + i * 256;
        t[i] = (s < len) ? __expf(v[i] - mm) : 0.0f;
        L += t[i];
    }
#pragma unroll
    for (int o = 16; o > 0; o >>= 1) L += __shfl_xor_sync(0xffffffffu, L, o);
    __syncthreads();
    if (lane == 0) red[wid] = L;
    __syncthreads();
    float Lt = 0.0f;
#pragma unroll
    for (int i = 0; i < 8; i++) Lt += red[i];
    float inv = __fdividef(1.0f, Lt);

#pragma unroll
    for (int i = 0; i < 8; i++) {
        int s = tid + i * 256;
        float a = t[i] * inv;
        g_attn[(size_t)b * S_ + s] = a;
        if (attn_out) attn_out[(size_t)b * S_ + s] = a;
    }
}

// ---------------------------------------------------------------------------
// Kernel 4: weighted-sum partials. grid (32, B): s-chunks of 64, 4-way unroll.
// ---------------------------------------------------------------------------
__global__ __launch_bounds__(128) void wsum_kernel(const float* __restrict__ A,
                                                   const int* __restrict__ lengths) {
    int q = blockIdx.x, b = blockIdx.y;
    int tid = threadIdx.x;
    int len = lengths[b];
    int nv = len - q * 64;
    nv = (nv > 64) ? 64 : nv;

    float4 acc0 = make_float4(0.f, 0.f, 0.f, 0.f);
    float4 acc1 = make_float4(0.f, 0.f, 0.f, 0.f);
    if (nv > 0) {
        const float* Ab = A + ((size_t)b * S_ + q * 64) * E_ + tid * 4;
        const float* at = g_attn + (size_t)b * S_ + q * 64;
        int s = 0;
        for (; s + 4 <= nv; s += 4) {
            float w0 = at[s], w1 = at[s + 1], w2 = at[s + 2], w3 = at[s + 3];
            float4 a0 = *reinterpret_cast<const float4*>(Ab + (size_t)s * E_);
            float4 a1 = *reinterpret_cast<const float4*>(Ab + (size_t)(s + 1) * E_);
            float4 a2 = *reinterpret_cast<const float4*>(Ab + (size_t)(s + 2) * E_);
            float4 a3 = *reinterpret_cast<const float4*>(Ab + (size_t)(s + 3) * E_);
            acc0.x += w0 * a0.x + w2 * a2.x;
            acc0.y += w0 * a0.y + w2 * a2.y;
            acc0.z += w0 * a0.z + w2 * a2.z;
            acc0.w += w0 * a0.w + w2 * a2.w;
            acc1.x += w1 * a1.x + w3 * a3.x;
            acc1.y += w1 * a1.y + w3 * a3.y;
            acc1.z += w1 * a1.z + w3 * a3.z;
            acc1.w += w1 * a1.w + w3 * a3.w;
        }
        for (; s < nv; s++) {
            float w = at[s];
            float4 a = *reinterpret_cast<const float4*>(Ab + (size_t)s * E_);
            acc0.x += w * a.x; acc0.y += w * a.y; acc0.z += w * a.z; acc0.w += w * a.w;
        }
    }
    acc0.x += acc1.x; acc0.y += acc1.y; acc0.z += acc1.z; acc0.w += acc1.w;
    *reinterpret_cast<float4*>(g_part + ((size_t)(q * B_ + b)) * E_ + tid * 4) = acc0;
}

// ---------------------------------------------------------------------------
// Kernel 5: reduce 32 partials -> attention_features
// ---------------------------------------------------------------------------
__global__ void reduce_kernel(float* __restrict__ feat) {
    int b = blockIdx.x, e = threadIdx.x;
    float s = 0.0f;
#pragma unroll
    for (int q = 0; q < 32; q++) s += g_part[((size_t)(q * B_ + b)) * E_ + e];
    feat[b * E_ + e] = s;
}

// ---------------------------------------------------------------------------
extern "C" void kernel_launch(void* const* d_in, const int* in_sizes, int n_in,
                              void* d_out, int out_size) {
    const float* A        = (const float*)d_in[0];
    const int*   lengths  = (const int*)d_in[1];
    const float* context  = (const float*)d_in[2];
    const float* W_word   = (const float*)d_in[3];
    const float* b_word   = (const float*)d_in[4];
    const float* W_ctx    = (const float*)d_in[5];
    const float* b_ctx    = (const float*)d_in[6];
    const float* w_hidden = (const float*)d_in[7];

    float* out = (float*)d_out;
    float* feat_out = out;
    float* attn_out = (out_size >= B_ * E_ + B_ * S_) ? out + B_ * E_ : nullptr;

    // smem: max(tiles 61440B, epilogue 128*132*4=67584B) + ctx/wh 2048B
    const int SCORES_SMEM = 128 * LDWF * 4 + 2048;  // 69632
    cudaFuncSetAttribute(scores_kernel, cudaFuncAttributeMaxDynamicSharedMemorySize,
                         SCORES_SMEM);

    ctx_kernel<<<B_, H_>>>(context, W_ctx, b_ctx, b_word);

    dim3 g2(S_ / 128, B_);
    scores_kernel<<<g2, 512, SCORES_SMEM>>>(A, W_word, lengths, w_hidden);

    attn_softmax_kernel<<<B_, 256>>>(lengths, attn_out);

    dim3 g4(32, B_);
    wsum_kernel<<<g4, 128>>>(A, lengths);

    reduce_kernel<<<B_, E_>>>(feat_out);
}